// round 14
// baseline (speedup 1.0000x reference)
#include <cuda_runtime.h>
#include <cuda_fp16.h>
#include <math_constants.h>
#include <cstdint>

#define NB 32
#define NS 256
#define NH 768

#define KC 64            // fp16 elems per K-chunk (= 128 bytes/row, SW128 native)
#define NCHUNK (NH / KC) // 12
#define TM 64            // s-rows per CTA
#define TN 256           // t-cols per CTA (full row -> local softmax)
#define NSTAGE 2

// static smem region (first 8 KB), then 2 pipeline stages of 40 KB
#define OFF_SW   0           // sWL[256]: scl*exp(-alpha*d)*log2e
#define OFF_V    1024        // sV[256]: k_mask valid (1.0/0.0)
#define OFF_EX   2048        // exsp[256], exsv[256]  (2 KB)
#define OFF_STG  8192
#define TILE_AH  0
#define TILE_BH  8192
#define STG_BYTES 40960      // Ah8K + Bh32K
#define SMEM_TOTAL (OFF_STG + NSTAGE * STG_BYTES)   // 90112 B -> 2 CTAs/SM

// Scratch (no allocations allowed)
__device__ __half g_Qh[NB * NS * NH];
__device__ __half g_Kh[NB * NS * NH];
__device__ float g_denom[NB];
__device__ float g_alpha;
__device__ float g_scale;

// ---------------------------------------------------------------------------
// helpers
// ---------------------------------------------------------------------------
__device__ __forceinline__ uint32_t smem_u32(const void* p) {
    uint32_t a;
    asm("{ .reg .u64 t; cvta.to.shared.u64 t, %1; cvt.u32.u64 %0, t; }" : "=r"(a) : "l"(p));
    return a;
}
#define SWZ(x) ((x) ^ (((x) >> 3) & 0x70))

__device__ __forceinline__ void cpa16(uint32_t dst, const void* src) {
    asm volatile("cp.async.cg.shared.global [%0], [%1], 16;" :: "r"(dst), "l"(src));
}

__device__ __forceinline__ void ldsm_x4(uint32_t& r0, uint32_t& r1, uint32_t& r2,
                                        uint32_t& r3, uint32_t addr) {
    asm volatile("ldmatrix.sync.aligned.m8n8.x4.shared.b16 {%0,%1,%2,%3}, [%4];"
                 : "=r"(r0), "=r"(r1), "=r"(r2), "=r"(r3) : "r"(addr));
}

__device__ __forceinline__ void mma16816(float* c, const uint32_t* a, const uint32_t* b) {
    asm volatile(
        "mma.sync.aligned.m16n8k16.row.col.f32.f16.f16.f32 "
        "{%0,%1,%2,%3}, {%4,%5,%6,%7}, {%8,%9}, {%0,%1,%2,%3};"
        : "+f"(c[0]), "+f"(c[1]), "+f"(c[2]), "+f"(c[3])
        : "r"(a[0]), "r"(a[1]), "r"(a[2]), "r"(a[3]), "r"(b[0]), "r"(b[1]));
}

__device__ __forceinline__ float fast_exp2(float x) {
    float y;
    asm("ex2.approx.ftz.f32 %0, %1;" : "=f"(y) : "f"(x));
    return y;
}

// ---------------------------------------------------------------------------
// Fused norm + setup, warp-per-row.
// Blocks 0..2047: 8 warps each, warp w normalizes row blockIdx.x*8+w.
//   Lane loads 6 float4 (24 floats), warp-reduces sum-of-squares,
//   writes 6 uint2 of packed half2. No block barriers, no smem.
// Block 2048: zero output, per-i mask denominators, softplus/exp consts.
// ---------------------------------------------------------------------------
__global__ void norm_setup_kernel(const float* __restrict__ q,
                                  const float* __restrict__ k,
                                  const float* __restrict__ qm,
                                  const float* __restrict__ alpha_raw,
                                  const float* __restrict__ logit_scale,
                                  float* __restrict__ out)
{
    int t = threadIdx.x;                  // 256 threads
    int wid = t >> 5, lane = t & 31;

    if (blockIdx.x == 2 * NB * NS / 8) {
        // ---- setup block ----
        out[t] = 0.0f;
        out[t + 256] = 0.0f;
        out[t + 512] = 0.0f;
        out[t + 768] = 0.0f;

        #pragma unroll
        for (int r4 = 0; r4 < 4; r4++) {   // 8 warps x 4 i's
            int i = wid * 4 + r4;
            float s = 0.0f;
            #pragma unroll
            for (int tt = lane; tt < NS; tt += 32) s += qm[i * NS + tt];
            #pragma unroll
            for (int o = 16; o; o >>= 1) s += __shfl_xor_sync(0xffffffffu, s, o);
            if (lane == 0) g_denom[i] = fmaxf(s, 1.0f);
        }
        if (t == 0) {
            float a = alpha_raw[0];
            g_alpha = (a > 20.0f) ? a : log1pf(expf(a));
            g_scale = expf(logit_scale[0]);
        }
        return;
    }

    // ---- normalize: one warp per row ----
    int row = blockIdx.x * 8 + wid;       // 0 .. 16383
    bool isQ = row < NB * NS;
    int r = isQ ? row : row - NB * NS;
    const float4* src4 = (const float4*)((isQ ? q : k) + (size_t)r * NH);

    float4 v[6];
    float ss = 0.0f;
    #pragma unroll
    for (int cgk = 0; cgk < 6; cgk++) {
        v[cgk] = src4[lane + cgk * 32];
        ss += v[cgk].x * v[cgk].x + v[cgk].y * v[cgk].y
            + v[cgk].z * v[cgk].z + v[cgk].w * v[cgk].w;
    }
    #pragma unroll
    for (int o = 16; o; o >>= 1) ss += __shfl_xor_sync(0xffffffffu, ss, o);
    float inv = 1.0f / fmaxf(sqrtf(ss), 1e-12f);

    uint2* dst2 = (uint2*)((isQ ? g_Qh : g_Kh) + (size_t)r * NH);
    #pragma unroll
    for (int cgk = 0; cgk < 6; cgk++) {
        __half2 a = __floats2half2_rn(v[cgk].x * inv, v[cgk].y * inv);
        __half2 b = __floats2half2_rn(v[cgk].z * inv, v[cgk].w * inv);
        uint2 o2;
        o2.x = *(uint32_t*)&a;
        o2.y = *(uint32_t*)&b;
        dst2[lane + cgk * 32] = o2;
    }
}

// ---------------------------------------------------------------------------
// tile loaders: ROWS x 64 fp16 chunk -> SW128-swizzled smem via cp.async
// ---------------------------------------------------------------------------
template <int ROWS>
__device__ __forceinline__ void load_tile(uint32_t sdst, const __half* g,
                                          int k0, int tid)
{
    #pragma unroll
    for (int it = 0; it < ROWS * 8 / 256; it++) {
        int u = tid + it * 256;
        int row = u >> 3, c16 = u & 7;
        const void* src = g + (size_t)row * NH + k0 + c16 * 8;
        cpa16(sdst + SWZ(row * 128 + c16 * 16), src);
    }
}

__device__ __forceinline__ void load_chunk(uint32_t stg, int c,
                                           const __half* Ah, const __half* Bh,
                                           int tid)
{
    int k0 = c * KC;
    load_tile<TM>(stg + TILE_AH, Ah, k0, tid);
    load_tile<TN>(stg + TILE_BH, Bh, k0, tid);
    asm volatile("cp.async.commit_group;" ::: "memory");
}

// ---------------------------------------------------------------------------
// Main: pure-fp16 GEMM (64x256x768) + decayed masked softmax + score
// grid = (4, NB(j), NB(i)), 256 threads = 8 warps (2 m x 4 n), warp tile 32x64
// occ=2 (64-reg accumulator); proven R10/R12 two-barrier schedule, verbatim.
// ---------------------------------------------------------------------------
__global__ __launch_bounds__(256, 2)
void li_mma_kernel(const float* __restrict__ qm, const float* __restrict__ km,
                   float* __restrict__ out)
{
    extern __shared__ char smem[];
    uint32_t sb = smem_u32(smem);
    const int tid = threadIdx.x, wid = tid >> 5, lane = tid & 31;
    const int wm = wid >> 2, wn = wid & 3;       // warp grid 2 x 4
    const int i = blockIdx.z, j = blockIdx.y, mt = blockIdx.x;
    const int s0 = mt * TM;

    // tables
    float* sWL = (float*)(smem + OFF_SW);
    float* sV  = (float*)(smem + OFF_V);
    float* exsp = (float*)(smem + OFF_EX);        // [4][64]
    float* exsv = exsp + 256;                     // [4][64]
    const float scl = g_scale;
    const float LOG2E = 1.4426950408889634f;
    sWL[tid] = scl * __expf(-g_alpha * (float)tid) * LOG2E;
    sV[tid]  = (km[j * NS + tid] > 0.0f) ? 1.0f : 0.0f;

    const __half* Ah = g_Qh + (size_t)(i * NS + s0) * NH;
    const __half* Bh = g_Kh + (size_t)(j * NS) * NH;

    // prologue: chunks 0,1 -> stages 0,1 (prefetch distance 2)
    load_chunk(sb + OFF_STG + 0 * STG_BYTES, 0, Ah, Bh, tid);
    load_chunk(sb + OFF_STG + 1 * STG_BYTES, 1, Ah, Bh, tid);

    float acc[2][8][4];
    #pragma unroll
    for (int a = 0; a < 2; a++)
        #pragma unroll
        for (int b = 0; b < 8; b++)
            #pragma unroll
            for (int c = 0; c < 4; c++) acc[a][b][c] = 0.0f;

    // per-lane ldmatrix addressing constants
    const int mm = lane >> 3, lr = lane & 7;
    const int rowA = wm * 32 + (mm & 1) * 8 + lr;          // + mi*16
    const int kbA  = ((mm >> 1) & 1) * 16;                 // + kk*32
    const int rowB = wn * 64 + ((mm >> 1) & 1) * 8 + lr;   // + jb*16
    const int kbB  = (mm & 1) * 16;                        // + kk*32

    for (int c = 0; c < NCHUNK; c++) {
        const uint32_t stg = sb + OFF_STG + (c & 1) * STG_BYTES;
        if (c < NCHUNK - 1) asm volatile("cp.async.wait_group 1;" ::: "memory");
        else                asm volatile("cp.async.wait_group 0;" ::: "memory");
        __syncthreads();

        #pragma unroll
        for (int kk = 0; kk < 4; kk++) {
            uint32_t ah[2][4];
            #pragma unroll
            for (int mi = 0; mi < 2; mi++) {
                uint32_t off = SWZ(((rowA + mi * 16) << 7) + kk * 32 + kbA);
                ldsm_x4(ah[mi][0], ah[mi][1], ah[mi][2], ah[mi][3], stg + TILE_AH + off);
            }
            #pragma unroll
            for (int half = 0; half < 2; half++) {
                uint32_t bh[4][2];
                #pragma unroll
                for (int jb = 0; jb < 2; jb++) {
                    uint32_t off = SWZ(((rowB + (half * 2 + jb) * 16) << 7) + kk * 32 + kbB);
                    ldsm_x4(bh[jb*2][0], bh[jb*2][1], bh[jb*2+1][0], bh[jb*2+1][1],
                            stg + TILE_BH + off);
                }
                #pragma unroll
                for (int mi = 0; mi < 2; mi++)
                    #pragma unroll
                    for (int nj = 0; nj < 4; nj++)
                        mma16816(acc[mi][half * 4 + nj], ah[mi], bh[nj]);
            }
        }
        __syncthreads();
        if (c + 2 < NCHUNK) load_chunk(stg, c + 2, Ah, Bh, tid);
    }

    // ---- Epilogue: single-pass softmax with constant shift M = scale ----
    // logits l = scl*a*w[d] (valid), |sim|<=1, decay<=1 => l <= scl always.
    const float msub = scl * LOG2E;
    const int tb = wn * 64 + (lane & 3) * 2;
    float vreg[16];
    #pragma unroll
    for (int nj = 0; nj < 8; nj++) {
        vreg[nj * 2]     = sV[tb + nj * 8];
        vreg[nj * 2 + 1] = sV[tb + nj * 8 + 1];
    }

    #pragma unroll
    for (int mi = 0; mi < 2; mi++) {
        #pragma unroll
        for (int rs = 0; rs < 2; rs++) {
            const int lrow = wm * 32 + mi * 16 + rs * 8 + (lane >> 2);
            const int s = s0 + lrow;
            float sp = 0.0f, sv = 0.0f;
            #pragma unroll
            for (int nj = 0; nj < 8; nj++) {
                #pragma unroll
                for (int cc2 = 0; cc2 < 2; cc2++) {
                    int t = tb + nj * 8 + cc2;
                    float a = acc[mi][nj][rs * 2 + cc2];
                    int d = s - t; d = (d < 0) ? -d : d;
                    float x = fmaf(a, sWL[d], -msub);
                    float e = fast_exp2(x) * vreg[nj * 2 + cc2];
                    sp += e;
                    sv = fmaf(e, a, sv);
                }
            }
            sp += __shfl_xor_sync(0xffffffffu, sp, 1);
            sp += __shfl_xor_sync(0xffffffffu, sp, 2);
            sv += __shfl_xor_sync(0xffffffffu, sv, 1);
            sv += __shfl_xor_sync(0xffffffffu, sv, 2);
            if ((lane & 3) == 0) {
                exsp[wn * 64 + lrow] = sp;
                exsv[wn * 64 + lrow] = sv;
            }
        }
    }
    __syncthreads();

    if (tid < 64) {
        float sp = exsp[tid] + exsp[64 + tid] + exsp[128 + tid] + exsp[192 + tid];
        float sv = exsv[tid] + exsv[64 + tid] + exsv[128 + tid] + exsv[192 + tid];
        float sc = (sp > 0.0f) ? (sv / sp) : 0.0f;
        float contrib = sc * qm[i * NS + s0 + tid];
        #pragma unroll
        for (int o = 16; o; o >>= 1)
            contrib += __shfl_xor_sync(0xffffffffu, contrib, o);
        if ((tid & 31) == 0) atomicAdd(&out[i * NB + j], contrib / g_denom[i]);
    }
}

// ---------------------------------------------------------------------------
extern "C" void kernel_launch(void* const* d_in, const int* in_sizes, int n_in,
                              void* d_out, int out_size)
{
    const float* q  = (const float*)d_in[0];
    const float* k  = (const float*)d_in[1];
    const float* qm = (const float*)d_in[2];
    const float* km = (const float*)d_in[3];
    const float* ar = (const float*)d_in[4];
    const float* ls = (const float*)d_in[5];
    float* out = (float*)d_out;

    cudaFuncSetAttribute(li_mma_kernel,
                         cudaFuncAttributeMaxDynamicSharedMemorySize, SMEM_TOTAL);

    norm_setup_kernel<<<2 * NB * NS / 8 + 1, 256>>>(q, k, qm, ar, ls, out);
    dim3 grid(NS / TM, NB, NB);
    li_mma_kernel<<<grid, 256, SMEM_TOTAL>>>(qm, km, out);
}

// round 15
// speedup vs baseline: 1.5156x; 1.5156x over previous
#include <cuda_runtime.h>
#include <cuda_fp16.h>
#include <math_constants.h>
#include <cstdint>

#define NB 32
#define NS 256
#define NH 768

#define KC 64            // fp16 elems per K-chunk (= 128 bytes/row, SW128 native)
#define NCHUNK (NH / KC) // 12
#define TM 64            // s-rows per CTA
#define TN 256           // t-cols per CTA (full row -> local softmax)
#define NSTAGE 2

// static smem region (first 8 KB), then 2 pipeline stages of 40 KB
#define OFF_SW   0           // sWL[256]: scl*exp(-alpha*d)*log2e
#define OFF_V    1024        // sV[256]: k_mask valid (1.0/0.0)
#define OFF_EX   2048        // exsp[256], exsv[256]  (2 KB)
#define OFF_STG  8192
#define TILE_AH  0
#define TILE_BH  8192
#define STG_BYTES 40960      // Ah8K + Bh32K
#define SMEM_TOTAL (OFF_STG + NSTAGE * STG_BYTES)   // 90112 B -> 2 CTAs/SM

// Scratch (no allocations allowed)
__device__ __half g_Qh[NB * NS * NH];
__device__ __half g_Kh[NB * NS * NH];
__device__ float g_denom[NB];
__device__ float g_alpha;
__device__ float g_scale;

// ---------------------------------------------------------------------------
// helpers
// ---------------------------------------------------------------------------
__device__ __forceinline__ uint32_t smem_u32(const void* p) {
    uint32_t a;
    asm("{ .reg .u64 t; cvta.to.shared.u64 t, %1; cvt.u32.u64 %0, t; }" : "=r"(a) : "l"(p));
    return a;
}
#define SWZ(x) ((x) ^ (((x) >> 3) & 0x70))

__device__ __forceinline__ void cpa16(uint32_t dst, const void* src) {
    asm volatile("cp.async.cg.shared.global [%0], [%1], 16;" :: "r"(dst), "l"(src));
}

__device__ __forceinline__ void ldsm_x4(uint32_t& r0, uint32_t& r1, uint32_t& r2,
                                        uint32_t& r3, uint32_t addr) {
    asm volatile("ldmatrix.sync.aligned.m8n8.x4.shared.b16 {%0,%1,%2,%3}, [%4];"
                 : "=r"(r0), "=r"(r1), "=r"(r2), "=r"(r3) : "r"(addr));
}

__device__ __forceinline__ void mma16816(float* c, const uint32_t* a, const uint32_t* b) {
    asm volatile(
        "mma.sync.aligned.m16n8k16.row.col.f32.f16.f16.f32 "
        "{%0,%1,%2,%3}, {%4,%5,%6,%7}, {%8,%9}, {%0,%1,%2,%3};"
        : "+f"(c[0]), "+f"(c[1]), "+f"(c[2]), "+f"(c[3])
        : "r"(a[0]), "r"(a[1]), "r"(a[2]), "r"(a[3]), "r"(b[0]), "r"(b[1]));
}

__device__ __forceinline__ float fast_exp2(float x) {
    float y;
    asm("ex2.approx.ftz.f32 %0, %1;" : "=f"(y) : "f"(x));
    return y;
}

// ---------------------------------------------------------------------------
// Fused norm + setup. Blocks 0..2*NB*NS-1: L2-normalize one row -> fp16.
// Block 2*NB*NS: zero output, per-i mask denominators, softplus/exp consts.
// ---------------------------------------------------------------------------
__global__ void norm_setup_kernel(const float* __restrict__ q,
                                  const float* __restrict__ k,
                                  const float* __restrict__ qm,
                                  const float* __restrict__ alpha_raw,
                                  const float* __restrict__ logit_scale,
                                  float* __restrict__ out)
{
    int row = blockIdx.x;
    int t = threadIdx.x;                  // 256 threads

    if (row == 2 * NB * NS) {
        // ---- setup block ----
        out[t] = 0.0f;
        out[t + 256] = 0.0f;
        out[t + 512] = 0.0f;
        out[t + 768] = 0.0f;

        int wid = t >> 5, lane = t & 31;  // 8 warps; each handles 4 i's
        #pragma unroll
        for (int r4 = 0; r4 < 4; r4++) {
            int i = wid * 4 + r4;
            float s = 0.0f;
            #pragma unroll
            for (int tt = lane; tt < NS; tt += 32) s += qm[i * NS + tt];
            #pragma unroll
            for (int o = 16; o; o >>= 1) s += __shfl_xor_sync(0xffffffffu, s, o);
            if (lane == 0) g_denom[i] = fmaxf(s, 1.0f);
        }
        if (t == 0) {
            float a = alpha_raw[0];
            g_alpha = (a > 20.0f) ? a : log1pf(expf(a));
            g_scale = expf(logit_scale[0]);
        }
        return;
    }

    // ---- normalize block ----
    bool isQ = row < NB * NS;
    int r = isQ ? row : row - NB * NS;
    const float* src = (isQ ? q : k) + (size_t)r * NH;
    __half* dh = (isQ ? g_Qh : g_Kh) + (size_t)r * NH;

    float v0 = src[t], v1 = src[t + 256], v2 = src[t + 512];
    float ss = v0 * v0 + v1 * v1 + v2 * v2;

    __shared__ float red[8];
    __shared__ float s_inv;
    #pragma unroll
    for (int o = 16; o; o >>= 1) ss += __shfl_xor_sync(0xffffffffu, ss, o);
    if ((t & 31) == 0) red[t >> 5] = ss;
    __syncthreads();
    if (t == 0) {
        float tot = 0.0f;
        #pragma unroll
        for (int w = 0; w < 8; w++) tot += red[w];
        s_inv = 1.0f / fmaxf(sqrtf(tot), 1e-12f);
    }
    __syncthreads();
    float inv = s_inv;
    dh[t]       = __float2half_rn(v0 * inv);
    dh[t + 256] = __float2half_rn(v1 * inv);
    dh[t + 512] = __float2half_rn(v2 * inv);
}

// ---------------------------------------------------------------------------
// tile loaders: ROWS x 64 fp16 chunk -> SW128-swizzled smem via cp.async
// ---------------------------------------------------------------------------
template <int ROWS>
__device__ __forceinline__ void load_tile(uint32_t sdst, const __half* g,
                                          int k0, int tid)
{
    #pragma unroll
    for (int it = 0; it < ROWS * 8 / 256; it++) {
        int u = tid + it * 256;
        int row = u >> 3, c16 = u & 7;
        const void* src = g + (size_t)row * NH + k0 + c16 * 8;
        cpa16(sdst + SWZ(row * 128 + c16 * 16), src);
    }
}

__device__ __forceinline__ void load_chunk(uint32_t stg, int c,
                                           const __half* Ah, const __half* Bh,
                                           int tid)
{
    int k0 = c * KC;
    load_tile<TM>(stg + TILE_AH, Ah, k0, tid);
    load_tile<TN>(stg + TILE_BH, Bh, k0, tid);
    asm volatile("cp.async.commit_group;" ::: "memory");
}

// ---------------------------------------------------------------------------
// Main: pure-fp16 GEMM (64x256x768) + decayed masked softmax + score
// grid = (4, NB(j), NB(i)), 256 threads = 8 warps (2 m x 4 n), warp tile 32x64
// occ=2 (64-reg accumulator); proven R10/R12 two-barrier schedule, verbatim.
// ---------------------------------------------------------------------------
__global__ __launch_bounds__(256, 2)
void li_mma_kernel(const float* __restrict__ qm, const float* __restrict__ km,
                   float* __restrict__ out)
{
    extern __shared__ char smem[];
    uint32_t sb = smem_u32(smem);
    const int tid = threadIdx.x, wid = tid >> 5, lane = tid & 31;
    const int wm = wid >> 2, wn = wid & 3;       // warp grid 2 x 4
    const int i = blockIdx.z, j = blockIdx.y, mt = blockIdx.x;
    const int s0 = mt * TM;

    // tables
    float* sWL = (float*)(smem + OFF_SW);
    float* sV  = (float*)(smem + OFF_V);
    float* exsp = (float*)(smem + OFF_EX);        // [4][64]
    float* exsv = exsp + 256;                     // [4][64]
    const float scl = g_scale;
    const float LOG2E = 1.4426950408889634f;
    sWL[tid] = scl * __expf(-g_alpha * (float)tid) * LOG2E;
    sV[tid]  = (km[j * NS + tid] > 0.0f) ? 1.0f : 0.0f;

    const __half* Ah = g_Qh + (size_t)(i * NS + s0) * NH;
    const __half* Bh = g_Kh + (size_t)(j * NS) * NH;

    // prologue: chunks 0,1 -> stages 0,1 (prefetch distance 2)
    load_chunk(sb + OFF_STG + 0 * STG_BYTES, 0, Ah, Bh, tid);
    load_chunk(sb + OFF_STG + 1 * STG_BYTES, 1, Ah, Bh, tid);

    float acc[2][8][4];
    #pragma unroll
    for (int a = 0; a < 2; a++)
        #pragma unroll
        for (int b = 0; b < 8; b++)
            #pragma unroll
            for (int c = 0; c < 4; c++) acc[a][b][c] = 0.0f;

    // per-lane ldmatrix addressing constants
    const int mm = lane >> 3, lr = lane & 7;
    const int rowA = wm * 32 + (mm & 1) * 8 + lr;          // + mi*16
    const int kbA  = ((mm >> 1) & 1) * 16;                 // + kk*32
    const int rowB = wn * 64 + ((mm >> 1) & 1) * 8 + lr;   // + jb*16
    const int kbB  = (mm & 1) * 16;                        // + kk*32

    for (int c = 0; c < NCHUNK; c++) {
        const uint32_t stg = sb + OFF_STG + (c & 1) * STG_BYTES;
        if (c < NCHUNK - 1) asm volatile("cp.async.wait_group 1;" ::: "memory");
        else                asm volatile("cp.async.wait_group 0;" ::: "memory");
        __syncthreads();

        #pragma unroll
        for (int kk = 0; kk < 4; kk++) {
            uint32_t ah[2][4];
            #pragma unroll
            for (int mi = 0; mi < 2; mi++) {
                uint32_t off = SWZ(((rowA + mi * 16) << 7) + kk * 32 + kbA);
                ldsm_x4(ah[mi][0], ah[mi][1], ah[mi][2], ah[mi][3], stg + TILE_AH + off);
            }
            #pragma unroll
            for (int half = 0; half < 2; half++) {
                uint32_t bh[4][2];
                #pragma unroll
                for (int jb = 0; jb < 2; jb++) {
                    uint32_t off = SWZ(((rowB + (half * 2 + jb) * 16) << 7) + kk * 32 + kbB);
                    ldsm_x4(bh[jb*2][0], bh[jb*2][1], bh[jb*2+1][0], bh[jb*2+1][1],
                            stg + TILE_BH + off);
                }
                #pragma unroll
                for (int mi = 0; mi < 2; mi++)
                    #pragma unroll
                    for (int nj = 0; nj < 4; nj++)
                        mma16816(acc[mi][half * 4 + nj], ah[mi], bh[nj]);
            }
        }
        __syncthreads();
        if (c + 2 < NCHUNK) load_chunk(stg, c + 2, Ah, Bh, tid);
    }

    // ---- Epilogue: single-pass softmax with constant shift M = scale ----
    // logits l = scl*a*w[d] (valid), |sim|<=1, decay<=1 => l <= scl always.
    const float msub = scl * LOG2E;
    const int tb = wn * 64 + (lane & 3) * 2;
    float vreg[16];
    #pragma unroll
    for (int nj = 0; nj < 8; nj++) {
        vreg[nj * 2]     = sV[tb + nj * 8];
        vreg[nj * 2 + 1] = sV[tb + nj * 8 + 1];
    }

    #pragma unroll
    for (int mi = 0; mi < 2; mi++) {
        #pragma unroll
        for (int rs = 0; rs < 2; rs++) {
            const int lrow = wm * 32 + mi * 16 + rs * 8 + (lane >> 2);
            const int s = s0 + lrow;
            float sp = 0.0f, sv = 0.0f;
            #pragma unroll
            for (int nj = 0; nj < 8; nj++) {
                #pragma unroll
                for (int cc2 = 0; cc2 < 2; cc2++) {
                    int t = tb + nj * 8 + cc2;
                    float a = acc[mi][nj][rs * 2 + cc2];
                    int d = s - t; d = (d < 0) ? -d : d;
                    float x = fmaf(a, sWL[d], -msub);
                    float e = fast_exp2(x) * vreg[nj * 2 + cc2];
                    sp += e;
                    sv = fmaf(e, a, sv);
                }
            }
            sp += __shfl_xor_sync(0xffffffffu, sp, 1);
            sp += __shfl_xor_sync(0xffffffffu, sp, 2);
            sv += __shfl_xor_sync(0xffffffffu, sv, 1);
            sv += __shfl_xor_sync(0xffffffffu, sv, 2);
            if ((lane & 3) == 0) {
                exsp[wn * 64 + lrow] = sp;
                exsv[wn * 64 + lrow] = sv;
            }
        }
    }
    __syncthreads();

    if (tid < 64) {
        float sp = exsp[tid] + exsp[64 + tid] + exsp[128 + tid] + exsp[192 + tid];
        float sv = exsv[tid] + exsv[64 + tid] + exsv[128 + tid] + exsv[192 + tid];
        float sc = (sp > 0.0f) ? (sv / sp) : 0.0f;
        float contrib = sc * qm[i * NS + s0 + tid];
        #pragma unroll
        for (int o = 16; o; o >>= 1)
            contrib += __shfl_xor_sync(0xffffffffu, contrib, o);
        if ((tid & 31) == 0) atomicAdd(&out[i * NB + j], contrib / g_denom[i]);
    }
}

// ---------------------------------------------------------------------------
extern "C" void kernel_launch(void* const* d_in, const int* in_sizes, int n_in,
                              void* d_out, int out_size)
{
    const float* q  = (const float*)d_in[0];
    const float* k  = (const float*)d_in[1];
    const float* qm = (const float*)d_in[2];
    const float* km = (const float*)d_in[3];
    const float* ar = (const float*)d_in[4];
    const float* ls = (const float*)d_in[5];
    float* out = (float*)d_out;

    cudaFuncSetAttribute(li_mma_kernel,
                         cudaFuncAttributeMaxDynamicSharedMemorySize, SMEM_TOTAL);

    norm_setup_kernel<<<2 * NB * NS + 1, 256>>>(q, k, qm, ar, ls, out);
    dim3 grid(NS / TM, NB, NB);
    li_mma_kernel<<<grid, 256, SMEM_TOTAL>>>(qm, km, out);
}